// round 17
// baseline (speedup 1.0000x reference)
#include <cuda_runtime.h>
#include <cuda_bf16.h>
#include <math_constants.h>

#define B_DIM 8
#define N_DIM 65536
#define C_DIM 80
#define NTOT (B_DIM * N_DIM)          // 524288 = 2^19
#define TOPK 4096
#define CONF_TH 4.0f
#define NMS_TH 0.5f
#define MAXCAND 8192

// ---------------- device scratch (no allocation allowed) ----------------
__device__ unsigned int        g_cnt;        // zero-init; reset in k_fix (single block!)
__device__ unsigned int        g_ncand;      // reset in k_fix
__device__ unsigned int        g_ncont;      // reset in k_fix
__device__ int                 g_M;
__device__ int                 g_cand[MAXCAND];          // anchors whose flag bit was set
__device__ unsigned int        g_flagbits[NTOT / 32];    // dedup; cleared in k_fix
__device__ unsigned long long  g_keys[TOPK];
__device__ int                 g_cont[TOPK];
__device__ unsigned long long  g_keep[64];
__device__ float4              g_sbox[TOPK];
__device__ int                 g_scat[TOPK];
__device__ int                 g_sim[TOPK];
__device__ int                 g_scls[TOPK];
__device__ float               g_ssc[TOPK];
__device__ unsigned long long  g_mask[(size_t)TOPK * 64];   // strict lower triangle

__device__ __forceinline__ void comb(float& s, int& c, float s2, int c2) {
    if (s2 > s || (s2 == s && c2 < c)) { s = s2; c = c2; }
}

// ---------------- kernel 1: exact threshold filter + inline exact argmax ----
// 256 threads/block, 8 coalesced LDG.128/thread (32 floats). Hot path is a
// pure FMNMX tree + one compare: trigger <=> some element > 4.0 (exact fp32,
// no false positives/negatives). Rare triggering threads (~1300 chip-wide)
// derive the owning anchor, dedup via a flag bit, reload ALL 20 float4s of
// that anchor from hot L2 (classes 4i..4i+3, sequential => first-max
// tie-break like jnp.argmax), and emit the sort key directly.
__global__ void __launch_bounds__(256) k_filter(const float* __restrict__ logits) {
    int t = threadIdx.x;
    size_t q0 = (size_t)blockIdx.x * 2048 + t;      // float4 index, stride 256
    const float4* lp = reinterpret_cast<const float4*>(logits);

    float4 v0 = __ldcs(lp + q0);
    float4 v1 = __ldcs(lp + q0 + 256);
    float4 v2 = __ldcs(lp + q0 + 512);
    float4 v3 = __ldcs(lp + q0 + 768);
    float4 v4 = __ldcs(lp + q0 + 1024);
    float4 v5 = __ldcs(lp + q0 + 1280);
    float4 v6 = __ldcs(lp + q0 + 1536);
    float4 v7 = __ldcs(lp + q0 + 1792);

    float m0 = fmaxf(fmaxf(v0.x, v0.y), fmaxf(v0.z, v0.w));
    float m1 = fmaxf(fmaxf(v1.x, v1.y), fmaxf(v1.z, v1.w));
    float m2 = fmaxf(fmaxf(v2.x, v2.y), fmaxf(v2.z, v2.w));
    float m3 = fmaxf(fmaxf(v3.x, v3.y), fmaxf(v3.z, v3.w));
    float m4 = fmaxf(fmaxf(v4.x, v4.y), fmaxf(v4.z, v4.w));
    float m5 = fmaxf(fmaxf(v5.x, v5.y), fmaxf(v5.z, v5.w));
    float m6 = fmaxf(fmaxf(v6.x, v6.y), fmaxf(v6.z, v6.w));
    float m7 = fmaxf(fmaxf(v7.x, v7.y), fmaxf(v7.z, v7.w));

    float m = fmaxf(fmaxf(fmaxf(m0, m1), fmaxf(m2, m3)),
                    fmaxf(fmaxf(m4, m5), fmaxf(m6, m7)));

    if (m > CONF_TH) {                               // rare path
        float mk[8] = {m0, m1, m2, m3, m4, m5, m6, m7};
        #pragma unroll
        for (int k = 0; k < 8; k++) {
            if (mk[k] > CONF_TH) {
                unsigned q = (unsigned)(q0 + (size_t)k * 256);
                unsigned a = q / 20;                 // 20 float4s per anchor
                unsigned old = atomicOr(&g_flagbits[a >> 5], 1u << (a & 31));
                if (!(old & (1u << (a & 31)))) {
                    // winner: exact max/argmax over the anchor's 80 logits
                    const float4* ap = lp + (size_t)a * 20;
                    float s = -CUDART_INF_F;
                    int cl = 0;
                    for (int i = 0; i < 20; i++) {   // ALL 20 float4s = 80 classes
                        float4 w = __ldg(ap + i);
                        comb(s, cl, w.x, i * 4 + 0);
                        comb(s, cl, w.y, i * 4 + 1);
                        comb(s, cl, w.z, i * 4 + 2);
                        comb(s, cl, w.w, i * 4 + 3);
                    }
                    unsigned pos = atomicAdd(&g_cnt, 1u);
                    if (pos < TOPK) {
                        g_keys[pos] =
                            ((unsigned long long)__float_as_uint(s) << 32) |
                            ((unsigned long long)(unsigned)((NTOT - 1) - a) << 7) |
                            (unsigned long long)(unsigned)cl;
                    }
                    unsigned cp = atomicAdd(&g_ncand, 1u);
                    if (cp < MAXCAND) g_cand[cp] = (int)a;
                }
            }
        }
    }
}

// ---------------- kernel 2: rank-based sort (keys distinct) + scatter --------
// rank(i) = #{j : key[j] > key[i]} -> sorted position; order-independent of
// the nondeterministic atomic compaction order => deterministic output.
__global__ void __launch_bounds__(1024) k_rank(const float* __restrict__ boxes) {
    __shared__ unsigned long long sk[TOPK];
    int t = threadIdx.x;
    int M = (int)min(g_cnt, (unsigned)TOPK);

    for (int i = t; i < M; i += 1024) sk[i] = g_keys[i];
    __syncthreads();

    int g = blockIdx.x * 1024 + t;
    if (g == 0) g_M = M;

    if (g < M) {
        unsigned long long me = sk[g];
        int r = 0, j = 0;
        for (; j + 4 <= M; j += 4) {
            r += (sk[j]     > me);
            r += (sk[j + 1] > me);
            r += (sk[j + 2] > me);
            r += (sk[j + 3] > me);
        }
        for (; j < M; j++) r += (sk[j] > me);

        float s    = __uint_as_float((unsigned)(me >> 32));
        unsigned a = (NTOT - 1) - (unsigned)((me >> 7) & 0x7FFFFu);
        int cls    = (int)(me & 0x7Fu);
        int b      = (int)(a >> 16);                 // N_DIM = 65536
        float4 bx  = reinterpret_cast<const float4*>(boxes)[a];
        g_sbox[r] = bx;
        g_scat[r] = b * C_DIM + cls;
        g_sim[r]  = b;
        g_scls[r] = cls;
        g_ssc[r]  = s;
    }
}

// ---------------- kernel 3: lower-triangle suppression bitmask ---------------
// Block = row i; warp owns word w, lane owns j (coalesced); ballot assembles
// the word. Diagonal word pre-masked to strictly j<i. Rows with any
// suppressor bit go on the contested list.
__global__ void __launch_bounds__(256) k_mask() {
    __shared__ int any;
    int M = g_M;
    int i = blockIdx.x;
    if (i >= M) return;
    int warp = threadIdx.x >> 5;
    int lane = threadIdx.x & 31;
    if (threadIdx.x == 0) any = 0;
    __syncthreads();

    float4 bi = g_sbox[i];
    int    ci = g_scat[i];
    float  ai = (bi.z - bi.x) * (bi.w - bi.y);

    int iw = i >> 6;
    for (int w = warp; w <= iw; w += 8) {
        int j0 = w << 6;
        unsigned long long bits = 0ULL;
        #pragma unroll
        for (int h = 0; h < 2; h++) {
            int j = j0 + h * 32 + lane;
            bool sup = false;
            if (j < M && __ldg(&g_scat[j]) == ci) {
                float4 bj = g_sbox[j];
                float w_ = fminf(bi.z, bj.z) - fmaxf(bi.x, bj.x);
                float h_ = fminf(bi.w, bj.w) - fmaxf(bi.y, bj.y);
                w_ = fmaxf(w_, 0.f); h_ = fmaxf(h_, 0.f);
                float inter = w_ * h_;
                float aj  = (bj.z - bj.x) * (bj.w - bj.y);
                float iou = inter / fmaxf(ai + aj - inter, 1e-12f);
                sup = iou > NMS_TH;
            }
            unsigned b = __ballot_sync(0xFFFFFFFFu, sup);
            bits |= ((unsigned long long)b) << (h * 32);
        }
        if (w == iw) {
            int r = i & 63;
            bits &= r ? ((1ULL << r) - 1ULL) : 0ULL;   // strictly lower triangle
        }
        if (lane == 0) {
            g_mask[(size_t)i * 64 + w] = bits;
            if (bits) atomicOr(&any, 1);
        }
    }
    __syncthreads();
    if (threadIdx.x == 0 && any) {
        unsigned pos = atomicAdd(&g_ncont, 1u);
        g_cont[pos] = i;
    }
}

// ---------------- kernel 4: contested-only greedy fixpoint + state reset -----
// keep[i]=1 is stable for rows with an empty mask; only contested rows can
// change. DAG over j<i => synchronous iteration converges to the unique
// greedy fixpoint; an unchanged round certifies it.
// SINGLE BLOCK: also owns ALL cross-replay state cleanup (dedup flag bits via
// the candidate list + counters), ordered by __syncthreads — no inter-block
// race (the k_out-based cleanup raced block 0's counter reset against other
// blocks' reads and leaked flag bits across graph replays).
__global__ void __launch_bounds__(1024) k_fix() {
    __shared__ unsigned long long kw[64];
    __shared__ unsigned char     nkb[TOPK];
    __shared__ int               changed;
    int t = threadIdx.x;
    int M  = g_M;
    int nc = (int)g_ncont;

    if (t < 64) {
        int lo = t << 6;
        unsigned long long wb;
        if (M >= lo + 64)      wb = ~0ULL;
        else if (M <= lo)      wb = 0ULL;
        else                   wb = (1ULL << (M - lo)) - 1ULL;
        kw[t] = wb;
    }
    __syncthreads();

    for (int round = 0; round < TOPK && nc; round++) {
        if (t == 0) changed = 0;
        __syncthreads();
        for (int c = t; c < nc; c += 1024) {
            int i = g_cont[c];
            const unsigned long long* row = &g_mask[(size_t)i * 64];
            int iw = i >> 6;
            unsigned long long supp = 0ULL;
            for (int w = 0; w <= iw; w++) supp |= row[w] & kw[w];
            nkb[c] = (supp == 0ULL) ? 1 : 0;
        }
        __syncthreads();
        for (int c = t; c < nc; c += 1024) {
            int i = g_cont[c];
            unsigned long long bit = 1ULL << (i & 63);
            bool cur = (kw[i >> 6] & bit) != 0ULL;
            bool nk  = nkb[c] != 0;
            if (cur != nk) {
                if (nk) atomicOr (&kw[i >> 6], bit);
                else    atomicAnd(&kw[i >> 6], ~bit);
                changed = 1;
            }
        }
        __syncthreads();
        if (!changed) break;
        __syncthreads();
    }

    if (t < 64) g_keep[t] = kw[t];

    // ---- cross-replay state cleanup (race-free: single block) ----
    __syncthreads();
    int ncand = (int)min(g_ncand, (unsigned)MAXCAND);
    for (int c = t; c < ncand; c += 1024) {
        unsigned a = (unsigned)g_cand[c];
        atomicAnd(&g_flagbits[a >> 5], ~(1u << (a & 31)));
    }
    __syncthreads();
    if (t == 0) { g_cnt = 0u; g_ncand = 0u; g_ncont = 0u; }
}

// ---------------- kernel 5: pure output ---------------------------------------
__global__ void __launch_bounds__(1024) k_out(float* __restrict__ out) {
    int i = blockIdx.x * 1024 + threadIdx.x;   // 0..4095
    int M = g_M;
    bool k = (i < M) && ((g_keep[i >> 6] >> (i & 63)) & 1ULL);

    float* o_img = out;
    float* o_box = out + TOPK;
    float* o_cls = out + TOPK + TOPK * 4;
    float* o_sc  = out + TOPK + TOPK * 4 + TOPK;

    if (k) {
        float4 bx = g_sbox[i];
        o_img[i]       = (float)g_sim[i];
        o_box[i*4 + 0] = bx.x;
        o_box[i*4 + 1] = bx.y;
        o_box[i*4 + 2] = bx.z;
        o_box[i*4 + 3] = bx.w;
        o_cls[i]       = (float)g_scls[i];
        o_sc[i]        = g_ssc[i];
    } else {
        o_img[i]       = -1.0f;
        o_box[i*4 + 0] = 0.0f;
        o_box[i*4 + 1] = 0.0f;
        o_box[i*4 + 2] = 0.0f;
        o_box[i*4 + 3] = 0.0f;
        o_cls[i]       = -1.0f;
        o_sc[i]        = 0.0f;
    }
}

// ---------------- launcher ----------------
extern "C" void kernel_launch(void* const* d_in, const int* in_sizes, int n_in,
                              void* d_out, int out_size) {
    const float* logits = (const float*)d_in[0];
    const float* boxes  = (const float*)d_in[1];
    float* out = (float*)d_out;

    // 10,485,760 float4s / (256 threads * 8 f4) = 5120 blocks
    k_filter<<<5120, 256>>>(logits);       // FMNMX filter + inline exact argmax
    k_rank<<<TOPK / 1024, 1024>>>(boxes);  // rank-sort + scatter
    k_mask<<<TOPK, 256>>>();               // lower-triangle bits + contested list
    k_fix<<<1, 1024>>>();                  // fixpoint + race-free state reset
    k_out<<<TOPK / 1024, 1024>>>(out);     // pure outputs
}